// round 9
// baseline (speedup 1.0000x reference)
#include <cuda_runtime.h>
#include <stdint.h>

#define BATCH 2048
#define KTOP  32
#define DDIM  768
#define DICT  24576
#define CONN  64

#define FT    64                 // up-feature tile width
#define NFT   (DICT / FT)        // 384 tiles
#define DH    128                // d-slice size
#define NSL   (DDIM / DH)        // 6 slices
#define CAP   256                // max pair records per tile bucket
#define SROW  (FT + 1)           // padded smem row stride (65)

#define NMATCH  2048
#define NBIASIT 768              // bias items, 32 rows each
#define NITEMS1 (NMATCH + NBIASIT)

#define NFUSE   (NSL * NFT)      // 2304
#define NEPI    256
#define NITEMS2 (NFUSE + NEPI)

#define GRID1   888              // 6 per SM, persistent
#define GRID2   888

__device__ float    g_bias[DICT];
__device__ unsigned g_bcnt[NFT];     // zeroed by K2 after use (self-maintaining)
__device__ unsigned g_done[NFT];     // arrival counters, self-resetting
// pair record: x = out position (b*K+i), y = down dict idx, z = up dict idx,
//              w = float bits of up_val[j]   (one record PER HIT)
__device__ uint4    g_bpairs[NFT * CAP];

// ---------------------------------------------------------------------------
// K1 (persistent): items [0, NBIASIT) = bias matvec chunks (32 rows each),
// items [NBIASIT, NITEMS1) = match blocks. Grid-stride mixes both streams.
// ---------------------------------------------------------------------------
__global__ __launch_bounds__(256) void k1_kernel(
    const float* __restrict__ up_vals,        // [B, K]
    const int*   __restrict__ up_indices,     // [B, K]
    const int*   __restrict__ down_indices,   // [B, K]
    const int*   __restrict__ connections,    // [DICT, C]
    const float* __restrict__ up_encoder_w,   // [DICT, D]
    const float* __restrict__ b_dec,          // [D]
    float*       __restrict__ out)            // [B, K]
{
    __shared__ float    s_b[DDIM];            // bias path
    __shared__ int      s_up_idx[KTOP];       // match path
    __shared__ float    s_up_val[KTOP];
    __shared__ int      s_down_idx[KTOP];
    __shared__ unsigned s_bm[DICT / 32];      // 3KB presence bitmap

    const int t    = threadIdx.x;
    const int warp = t >> 5;
    const int lane = t & 31;

    for (int item = blockIdx.x; item < NITEMS1; item += GRID1) {
        __syncthreads();                      // protect smem across iterations

        if (item < NBIASIT) {
            // -------------- bias path: 32 rows, 4 per warp (MLP 24) --------
            for (int i = t; i < DDIM; i += 256) s_b[i] = b_dec[i];
            __syncthreads();

            const int row0 = item * 32 + warp * 4;
            const float4* w  = reinterpret_cast<const float4*>(
                up_encoder_w + (size_t)row0 * DDIM);
            const float4* bb = reinterpret_cast<const float4*>(s_b);
            const int RS = DDIM / 4;           // 192
            float a0 = 0.f, a1 = 0.f, a2 = 0.f, a3 = 0.f;
#pragma unroll
            for (int k = 0; k < DDIM / 128; k++) {
                int c = lane + 32 * k;
                float4 b  = bb[c];
                float4 v0 = w[0 * RS + c];
                float4 v1 = w[1 * RS + c];
                float4 v2 = w[2 * RS + c];
                float4 v3 = w[3 * RS + c];
                a0 += v0.x * b.x + v0.y * b.y + v0.z * b.z + v0.w * b.w;
                a1 += v1.x * b.x + v1.y * b.y + v1.z * b.z + v1.w * b.w;
                a2 += v2.x * b.x + v2.y * b.y + v2.z * b.z + v2.w * b.w;
                a3 += v3.x * b.x + v3.y * b.y + v3.z * b.z + v3.w * b.w;
            }
#pragma unroll
            for (int o = 16; o > 0; o >>= 1) {
                a0 += __shfl_xor_sync(0xffffffffu, a0, o);
                a1 += __shfl_xor_sync(0xffffffffu, a1, o);
                a2 += __shfl_xor_sync(0xffffffffu, a2, o);
                a3 += __shfl_xor_sync(0xffffffffu, a3, o);
            }
            if (lane == 0) {
                g_bias[row0 + 0] = a0;
                g_bias[row0 + 1] = a1;
                g_bias[row0 + 2] = a2;
                g_bias[row0 + 3] = a3;
            }
            continue;
        }

        // -------------- match path: rare-hit bitmap filter -----------------
        const int b = item - NBIASIT;

#pragma unroll
        for (int r = 0; r < (DICT / 32) / 256; r++)
            s_bm[t + 256 * r] = 0u;

        if (t < KTOP) {
            int ui = up_indices[b * KTOP + t];
            s_up_idx[t]   = ui;
            s_up_val[t]   = up_vals[b * KTOP + t];
            s_down_idx[t] = down_indices[b * KTOP + t];
            out[b * KTOP + t] = 0.f;          // base; everything adds atomically
        }
        __syncthreads();

        if (t < KTOP)
            atomicOr(&s_bm[(unsigned)s_up_idx[t] >> 5], 1u << (s_up_idx[t] & 31));
        __syncthreads();

        // 32 rows x 16 int4 = 512 items streamed through the bitmap.
#pragma unroll
        for (int it = t; it < KTOP * (CONN / 4); it += 256) {
            int i = it >> 4;
            int q = it & 15;
            int di = s_down_idx[i];
            int4 a = reinterpret_cast<const int4*>(
                connections + (size_t)di * CONN)[q];
            int av[4] = {a.x, a.y, a.z, a.w};
#pragma unroll
            for (int s4 = 0; s4 < 4; s4++) {
                int v = av[s4];
                bool hit = false;
                if (v >= 0)
                    hit = (s_bm[(unsigned)v >> 5] >> (v & 31)) & 1u;
                if (hit) {
                    // rare: resolve matching j's (handles duplicate indices)
                    for (int j = 0; j < KTOP; j++) {
                        if (s_up_idx[j] == v) {
                            unsigned pos = atomicAdd(&g_bcnt[(unsigned)v >> 6], 1u);
                            if (pos < CAP) {
                                uint4 rec;
                                rec.x = (unsigned)(b * KTOP + i);
                                rec.y = (unsigned)di;
                                rec.z = (unsigned)v;
                                rec.w = __float_as_uint(s_up_val[j]);
                                g_bpairs[((unsigned)v >> 6) * CAP + pos] = rec;
                            }
                        }
                    }
                }
            }
        }
    }
}

// ---------------------------------------------------------------------------
// K2 (persistent): items [0, NFUSE) = fused (tile, slice) slab dots,
// items [NFUSE, NITEMS2) = bias-gather epilogue chunks.
// ---------------------------------------------------------------------------
__global__ __launch_bounds__(256) void k2_kernel(
    const float* __restrict__ up_decoder_w,   // [D, DICT]
    const float* __restrict__ down_encoder_w, // [DICT, D]
    const int*   __restrict__ up_indices,     // [B*K]
    float*       __restrict__ out)            // [B*K]
{
    extern __shared__ float s[];               // [DH][SROW] slab
    __shared__ unsigned s_cnt;

    const int t    = threadIdx.x;
    const int warp = t >> 5;
    const int lane = t & 31;

    for (int item = blockIdx.x; item < NITEMS2; item += GRID2) {
        __syncthreads();                      // protect smem across iterations

        if (item >= NFUSE) {
            // -------------- epilogue path: add bias base -------------------
            int i = (item - NFUSE) * 256 + t;
            atomicAdd(&out[i], g_bias[up_indices[i]]);
            continue;
        }

        // -------------- fused path -----------------------------------------
        const int tile  = item / NSL;
        const int slice = item % NSL;

        // Snapshot count; barrier so every thread owns it; THEN signal
        // arrival (last arriving slice-block resets counters for next replay).
        if (t == 0) s_cnt = g_bcnt[tile];
        __syncthreads();
        const unsigned cnt_raw = s_cnt;
        __syncthreads();                      // all reads done before reset
        if (t == 0) {
            unsigned old = atomicAdd(&g_done[tile], 1u);
            if (old == NSL - 1) {
                g_bcnt[tile] = 0u;
                g_done[tile] = 0u;
            }
        }
        const int cnt = (int)(cnt_raw < CAP ? cnt_raw : CAP);
        if (cnt == 0) continue;

        const int f0 = tile * FT;
        const int d0 = slice * DH;

        // Load slab: DH x FT = 2048 float4 / 256 threads = 8 each, coalesced.
        const float4* src = reinterpret_cast<const float4*>(
            up_decoder_w + (size_t)d0 * DICT + f0);
        const int RS4 = DICT / 4;
#pragma unroll
        for (int it = 0; it < (DH * FT / 4) / 256; it++) {
            int idx = t + 256 * it;
            int row = idx >> 4;               // / (FT/4)
            int c4  = idx & 15;
            float4 v = src[(size_t)row * RS4 + c4];
            float* dst = &s[row * SROW + c4 * 4];
            dst[0] = v.x; dst[1] = v.y; dst[2] = v.z; dst[3] = v.w;
        }
        __syncthreads();

        for (int p = warp; p < cnt; p += 8) {
            uint4 rec = g_bpairs[tile * CAP + p];
            const int fl = (int)rec.z - f0;
            const float* drow = down_encoder_w + (size_t)rec.y * DDIM + d0;
            float acc = 0.f;
#pragma unroll
            for (int m = 0; m < DH / 32; m++) {   // 4 iters, conflict-free smem
                int dd = lane + 32 * m;
                acc += s[dd * SROW + fl] * drow[dd];
            }
#pragma unroll
            for (int o = 16; o > 0; o >>= 1)
                acc += __shfl_xor_sync(0xffffffffu, acc, o);
            if (lane == 0)
                atomicAdd(&out[rec.x], acc * __uint_as_float(rec.w));
        }
    }
}

// ---------------------------------------------------------------------------
extern "C" void kernel_launch(void* const* d_in, const int* in_sizes, int n_in,
                              void* d_out, int out_size)
{
    const float* up_vals        = (const float*)d_in[0];
    const float* up_decoder_w   = (const float*)d_in[1];
    const float* down_encoder_w = (const float*)d_in[2];
    const float* up_encoder_w   = (const float*)d_in[3];
    const float* b_dec          = (const float*)d_in[4];
    const int*   up_indices     = (const int*)d_in[5];
    const int*   down_indices   = (const int*)d_in[6];
    const int*   connections    = (const int*)d_in[7];
    float*       out            = (float*)d_out;

    const int smem = DH * SROW * sizeof(float);  // 33,280 B dynamic
    static bool attr_set = false;
    if (!attr_set) {
        cudaFuncSetAttribute(k2_kernel,
                             cudaFuncAttributeMaxDynamicSharedMemorySize, smem);
        attr_set = true;
    }

    k1_kernel<<<GRID1, 256>>>(up_vals, up_indices, down_indices, connections,
                              up_encoder_w, b_dec, out);
    k2_kernel<<<GRID2, 256, smem>>>(up_decoder_w, down_encoder_w, up_indices, out);
}

// round 10
// speedup vs baseline: 1.1223x; 1.1223x over previous
#include <cuda_runtime.h>
#include <stdint.h>

#define BATCH 2048
#define KTOP  32
#define DDIM  768
#define DICT  24576
#define CONN  64

#define NMATCH 2048
#define NK1    3072              // (bid&3)==3 -> bias (768), else match slot (2304, 2048 used)

#define NK2      2560            // bid%10==9 -> epilogue (256), else pair blocks (2304)
#define NPAIRBLK 2304
#define MAXREC   65536

__device__ float    g_bias[DICT];
__device__ unsigned g_npairs;        // flat record count; self-resetting
__device__ unsigned g_done;          // arrival counter for reset; self-resetting
// pair record: x = out position (b*K+i), y = down dict idx, z = up dict idx,
//              w = float bits of up_val[j]   (one record PER HIT)
__device__ uint4    g_recs[MAXREC];

// ---------------------------------------------------------------------------
// K1: match (latency-bound) co-scheduled with bias matvec (DRAM-bound), 3:1.
// ---------------------------------------------------------------------------
__global__ __launch_bounds__(256) void k1_kernel(
    const float* __restrict__ up_vals,        // [B, K]
    const int*   __restrict__ up_indices,     // [B, K]
    const int*   __restrict__ down_indices,   // [B, K]
    const int*   __restrict__ connections,    // [DICT, C]
    const float* __restrict__ up_encoder_w,   // [DICT, D]
    const float* __restrict__ b_dec,          // [D]
    float*       __restrict__ out)            // [B, K]
{
    __shared__ float    s_b[DDIM];            // bias path
    __shared__ int      s_up_idx[KTOP];       // match path
    __shared__ float    s_up_val[KTOP];
    __shared__ int      s_down_idx[KTOP];
    __shared__ unsigned s_bm[DICT / 32];      // 3KB presence bitmap

    const int bid  = blockIdx.x;
    const int t    = threadIdx.x;
    const int warp = t >> 5;
    const int lane = t & 31;

    if ((bid & 3) == 3) {
        // ----------------- bias path: 32 rows, 4 per warp (MLP 24) ---------
        for (int i = t; i < DDIM; i += 256) s_b[i] = b_dec[i];
        __syncthreads();

        const int row0 = (bid >> 2) * 32 + warp * 4;
        const float4* w  = reinterpret_cast<const float4*>(
            up_encoder_w + (size_t)row0 * DDIM);
        const float4* bb = reinterpret_cast<const float4*>(s_b);
        const int RS = DDIM / 4;               // 192
        float a0 = 0.f, a1 = 0.f, a2 = 0.f, a3 = 0.f;
#pragma unroll
        for (int k = 0; k < DDIM / 128; k++) { // 6 iters, 24 indep LDG.128
            int c = lane + 32 * k;
            float4 b  = bb[c];
            float4 v0 = w[0 * RS + c];
            float4 v1 = w[1 * RS + c];
            float4 v2 = w[2 * RS + c];
            float4 v3 = w[3 * RS + c];
            a0 += v0.x * b.x + v0.y * b.y + v0.z * b.z + v0.w * b.w;
            a1 += v1.x * b.x + v1.y * b.y + v1.z * b.z + v1.w * b.w;
            a2 += v2.x * b.x + v2.y * b.y + v2.z * b.z + v2.w * b.w;
            a3 += v3.x * b.x + v3.y * b.y + v3.z * b.z + v3.w * b.w;
        }
#pragma unroll
        for (int o = 16; o > 0; o >>= 1) {
            a0 += __shfl_xor_sync(0xffffffffu, a0, o);
            a1 += __shfl_xor_sync(0xffffffffu, a1, o);
            a2 += __shfl_xor_sync(0xffffffffu, a2, o);
            a3 += __shfl_xor_sync(0xffffffffu, a3, o);
        }
        if (lane == 0) {
            g_bias[row0 + 0] = a0;
            g_bias[row0 + 1] = a1;
            g_bias[row0 + 2] = a2;
            g_bias[row0 + 3] = a3;
        }
        return;
    }

    // ----------------- match path: rare-hit bitmap filter ------------------
    const int b = (bid >> 2) * 3 + (bid & 3);  // 0..2303
    if (b >= NMATCH) return;

#pragma unroll
    for (int r = 0; r < (DICT / 32) / 256; r++)
        s_bm[t + 256 * r] = 0u;

    if (t < KTOP) {
        int ui = up_indices[b * KTOP + t];
        s_up_idx[t]   = ui;
        s_up_val[t]   = up_vals[b * KTOP + t];
        s_down_idx[t] = down_indices[b * KTOP + t];
        out[b * KTOP + t] = 0.f;              // base; everything adds atomically
    }
    __syncthreads();

    if (t < KTOP)
        atomicOr(&s_bm[(unsigned)s_up_idx[t] >> 5], 1u << (s_up_idx[t] & 31));
    __syncthreads();

    // 32 rows x 16 int4 = 512 items streamed through the bitmap.
#pragma unroll
    for (int item = t; item < KTOP * (CONN / 4); item += 256) {
        int i = item >> 4;
        int q = item & 15;
        int di = s_down_idx[i];
        int4 a = reinterpret_cast<const int4*>(connections + (size_t)di * CONN)[q];
        int av[4] = {a.x, a.y, a.z, a.w};
#pragma unroll
        for (int s = 0; s < 4; s++) {
            int v = av[s];
            bool hit = false;
            if (v >= 0)
                hit = (s_bm[(unsigned)v >> 5] >> (v & 31)) & 1u;
            if (hit) {
                // rare (~0.23% of slots): resolve matching j's (handles dups)
                for (int j = 0; j < KTOP; j++) {
                    if (s_up_idx[j] == v) {
                        unsigned pos = atomicAdd(&g_npairs, 1u);
                        if (pos < MAXREC) {
                            uint4 rec;
                            rec.x = (unsigned)(b * KTOP + i);
                            rec.y = (unsigned)di;
                            rec.z = (unsigned)v;
                            rec.w = __float_as_uint(s_up_val[j]);
                            g_recs[pos] = rec;
                        }
                    }
                }
            }
        }
    }
}

// ---------------------------------------------------------------------------
// K2: direct strided pair dots (one warp per record, grid-stride) co-scheduled
// with the bias-gather epilogue. Flat counter self-resets after all pair
// blocks have snapshotted it (read -> barrier -> arrive ordering).
// ---------------------------------------------------------------------------
__global__ __launch_bounds__(256) void k2_kernel(
    const float* __restrict__ up_decoder_w,   // [D, DICT]  (column access)
    const float* __restrict__ down_encoder_w, // [DICT, D]  (row access)
    const int*   __restrict__ up_indices,     // [B*K]
    float*       __restrict__ out)            // [B*K]
{
    __shared__ unsigned s_np;

    const int bid = blockIdx.x;
    const int t   = threadIdx.x;

    if (bid % 10 == 9) {
        // ----------------- epilogue path: add bias base --------------------
        int i = (bid / 10) * 256 + t;
        atomicAdd(&out[i], g_bias[up_indices[i]]);
        return;
    }

    // ----------------- pair path -------------------------------------------
    // Snapshot count; barrier; THEN signal arrival. Last of the NPAIRBLK
    // blocks resets the counters for the next graph replay.
    if (t == 0) s_np = g_npairs;
    __syncthreads();
    const unsigned np_raw = s_np;
    if (t == 0) {
        unsigned old = atomicAdd(&g_done, 1u);
        if (old == NPAIRBLK - 1) {
            g_npairs = 0u;
            g_done   = 0u;
        }
    }
    const unsigned np = np_raw < MAXREC ? np_raw : MAXREC;

    const int pblk = (bid / 10) * 9 + (bid % 10);   // 0..NPAIRBLK-1
    const int warp = t >> 5;
    const int lane = t & 31;
    const unsigned warp_id = (unsigned)pblk * 8 + warp;
    const unsigned nwarps  = NPAIRBLK * 8;

    for (unsigned p = warp_id; p < np; p += nwarps) {
        uint4 rec = g_recs[p];
        const float* drow = down_encoder_w + (size_t)rec.y * DDIM;   // coalesced
        const float* ucol = up_decoder_w + rec.z;                    // stride DICT
        float a0 = 0.f, a1 = 0.f;
#pragma unroll
        for (int k = 0; k < DDIM / 64; k++) {        // 12 iters, 2 indep chains
            int d0 = lane + 64 * k;
            int d1 = d0 + 32;
            a0 += drow[d0] * ucol[(size_t)d0 * DICT];
            a1 += drow[d1] * ucol[(size_t)d1 * DICT];
        }
        float acc = a0 + a1;
#pragma unroll
        for (int o = 16; o > 0; o >>= 1) acc += __shfl_xor_sync(0xffffffffu, acc, o);
        if (lane == 0)
            atomicAdd(&out[rec.x], acc * __uint_as_float(rec.w));
    }
}

// ---------------------------------------------------------------------------
extern "C" void kernel_launch(void* const* d_in, const int* in_sizes, int n_in,
                              void* d_out, int out_size)
{
    const float* up_vals        = (const float*)d_in[0];
    const float* up_decoder_w   = (const float*)d_in[1];
    const float* down_encoder_w = (const float*)d_in[2];
    const float* up_encoder_w   = (const float*)d_in[3];
    const float* b_dec          = (const float*)d_in[4];
    const int*   up_indices     = (const int*)d_in[5];
    const int*   down_indices   = (const int*)d_in[6];
    const int*   connections    = (const int*)d_in[7];
    float*       out            = (float*)d_out;

    k1_kernel<<<NK1, 256>>>(up_vals, up_indices, down_indices, connections,
                            up_encoder_w, b_dec, out);
    k2_kernel<<<NK2, 256>>>(up_decoder_w, down_encoder_w, up_indices, out);
}

// round 11
// speedup vs baseline: 1.2896x; 1.1490x over previous
#include <cuda_runtime.h>
#include <stdint.h>

#define BATCH 2048
#define KTOP  32
#define DDIM  768
#define DICT  24576
#define CONN  64

#define FT    64                 // up-feature tile width
#define NFT   (DICT / FT)        // 384 tiles
#define DH    64                 // d-slice size (16.6KB slab -> 8 blocks/SM)
#define NSL   (DDIM / DH)        // 12 slices
#define CAP   256                // max pair records per tile bucket
#define SROW  (FT + 1)           // padded smem row stride (65)

#define NMATCH 2048
#define NK1    3072              // (bid&3)==3 -> bias (768), else match slot

#define NFUSE  (NSL * NFT)       // 4608
#define NEPI   256
#define NK2    4864              // bid%19==18 -> epilogue (256), else fused (4608)

__device__ float    g_bias[DICT];
__device__ unsigned g_bcnt[NFT];     // zeroed by K2 after use (self-maintaining)
__device__ unsigned g_done[NFT];     // arrival counters, self-resetting
// pair record: x = out position (b*K+i), y = down dict idx, z = up dict idx,
//              w = float bits of up_val[j]   (one record PER HIT)
__device__ uint4    g_bpairs[NFT * CAP];

// ---------------------------------------------------------------------------
// K1: match (latency-bound) co-scheduled with bias matvec (DRAM-bound), 3:1.
// ---------------------------------------------------------------------------
__global__ __launch_bounds__(256) void k1_kernel(
    const float* __restrict__ up_vals,        // [B, K]
    const int*   __restrict__ up_indices,     // [B, K]
    const int*   __restrict__ down_indices,   // [B, K]
    const int*   __restrict__ connections,    // [DICT, C]
    const float* __restrict__ up_encoder_w,   // [DICT, D]
    const float* __restrict__ b_dec,          // [D]
    float*       __restrict__ out)            // [B, K]
{
    __shared__ float    s_b[DDIM];            // bias path
    __shared__ int      s_up_idx[KTOP];       // match path
    __shared__ float    s_up_val[KTOP];
    __shared__ int      s_down_idx[KTOP];
    __shared__ unsigned s_bm[DICT / 32];      // 3KB presence bitmap

    const int bid  = blockIdx.x;
    const int t    = threadIdx.x;
    const int warp = t >> 5;
    const int lane = t & 31;

    if ((bid & 3) == 3) {
        // ----------------- bias path: 32 rows, 4 per warp (MLP 24) ---------
        for (int i = t; i < DDIM; i += 256) s_b[i] = b_dec[i];
        __syncthreads();

        const int row0 = (bid >> 2) * 32 + warp * 4;
        const float4* w  = reinterpret_cast<const float4*>(
            up_encoder_w + (size_t)row0 * DDIM);
        const float4* bb = reinterpret_cast<const float4*>(s_b);
        const int RS = DDIM / 4;               // 192
        float a0 = 0.f, a1 = 0.f, a2 = 0.f, a3 = 0.f;
#pragma unroll
        for (int k = 0; k < DDIM / 128; k++) { // 6 iters, 24 indep LDG.128
            int c = lane + 32 * k;
            float4 b  = bb[c];
            float4 v0 = w[0 * RS + c];
            float4 v1 = w[1 * RS + c];
            float4 v2 = w[2 * RS + c];
            float4 v3 = w[3 * RS + c];
            a0 += v0.x * b.x + v0.y * b.y + v0.z * b.z + v0.w * b.w;
            a1 += v1.x * b.x + v1.y * b.y + v1.z * b.z + v1.w * b.w;
            a2 += v2.x * b.x + v2.y * b.y + v2.z * b.z + v2.w * b.w;
            a3 += v3.x * b.x + v3.y * b.y + v3.z * b.z + v3.w * b.w;
        }
#pragma unroll
        for (int o = 16; o > 0; o >>= 1) {
            a0 += __shfl_xor_sync(0xffffffffu, a0, o);
            a1 += __shfl_xor_sync(0xffffffffu, a1, o);
            a2 += __shfl_xor_sync(0xffffffffu, a2, o);
            a3 += __shfl_xor_sync(0xffffffffu, a3, o);
        }
        if (lane == 0) {
            g_bias[row0 + 0] = a0;
            g_bias[row0 + 1] = a1;
            g_bias[row0 + 2] = a2;
            g_bias[row0 + 3] = a3;
        }
        return;
    }

    // ----------------- match path: rare-hit bitmap filter ------------------
    const int b = (bid >> 2) * 3 + (bid & 3);  // 0..2303
    if (b >= NMATCH) return;

#pragma unroll
    for (int r = 0; r < (DICT / 32) / 256; r++)
        s_bm[t + 256 * r] = 0u;

    if (t < KTOP) {
        int ui = up_indices[b * KTOP + t];
        s_up_idx[t]   = ui;
        s_up_val[t]   = up_vals[b * KTOP + t];
        s_down_idx[t] = down_indices[b * KTOP + t];
        out[b * KTOP + t] = 0.f;              // base; everything adds atomically
    }
    __syncthreads();

    if (t < KTOP)
        atomicOr(&s_bm[(unsigned)s_up_idx[t] >> 5], 1u << (s_up_idx[t] & 31));
    __syncthreads();

    // 32 rows x 16 int4 = 512 items streamed through the bitmap.
#pragma unroll
    for (int item = t; item < KTOP * (CONN / 4); item += 256) {
        int i = item >> 4;
        int q = item & 15;
        int di = s_down_idx[i];
        int4 a = reinterpret_cast<const int4*>(connections + (size_t)di * CONN)[q];
        int av[4] = {a.x, a.y, a.z, a.w};
#pragma unroll
        for (int s = 0; s < 4; s++) {
            int v = av[s];
            bool hit = false;
            if (v >= 0)
                hit = (s_bm[(unsigned)v >> 5] >> (v & 31)) & 1u;
            if (hit) {
                // rare (~0.23% of slots): resolve matching j's (handles dups)
                for (int j = 0; j < KTOP; j++) {
                    if (s_up_idx[j] == v) {
                        unsigned pos = atomicAdd(&g_bcnt[(unsigned)v >> 6], 1u);
                        if (pos < CAP) {
                            uint4 rec;
                            rec.x = (unsigned)(b * KTOP + i);
                            rec.y = (unsigned)di;
                            rec.z = (unsigned)v;
                            rec.w = __float_as_uint(s_up_val[j]);
                            g_bpairs[((unsigned)v >> 6) * CAP + pos] = rec;
                        }
                    }
                }
            }
        }
    }
}

// ---------------------------------------------------------------------------
// K2: fused slab dots (DRAM-bound) co-scheduled with bias-gather epilogue
// (latency-bound), 18:1. DH=64 slab -> full occupancy (8 blocks/SM).
// Counter reset: snapshot into smem (stable local copy), then arrive.
// ---------------------------------------------------------------------------
__global__ __launch_bounds__(256) void k2_kernel(
    const float* __restrict__ up_decoder_w,   // [D, DICT]
    const float* __restrict__ down_encoder_w, // [DICT, D]
    const int*   __restrict__ up_indices,     // [B*K]
    float*       __restrict__ out)            // [B*K]
{
    __shared__ float    s[DH * SROW];          // 16,640 B slab
    __shared__ unsigned s_cnt;

    const int bid = blockIdx.x;
    const int t   = threadIdx.x;

    if (bid % 19 == 18) {
        // ----------------- epilogue path: add bias base --------------------
        int i = (bid / 19) * 256 + t;
        atomicAdd(&out[i], g_bias[up_indices[i]]);
        return;
    }

    // ----------------- fused path ------------------------------------------
    const int fidx  = (bid / 19) * 18 + (bid % 19);  // 0..NFUSE-1
    const int tile  = fidx / NSL;
    const int slice = fidx % NSL;

    // Snapshot count into smem (stable), barrier, then signal arrival. The
    // last arriving slice-block resets counters for the next graph replay;
    // s_cnt is untouched by the reset so later readers are safe.
    if (t == 0) s_cnt = g_bcnt[tile];
    __syncthreads();
    const unsigned cnt_raw = s_cnt;
    if (t == 0) {
        unsigned old = atomicAdd(&g_done[tile], 1u);
        if (old == NSL - 1) {
            g_bcnt[tile] = 0u;
            g_done[tile] = 0u;
        }
    }
    const int cnt = (int)(cnt_raw < CAP ? cnt_raw : CAP);
    if (cnt == 0) return;

    const int f0 = tile * FT;
    const int d0 = slice * DH;

    // Load slab: DH x FT = 1024 float4 / 256 threads = 4 each, coalesced.
    const float4* src = reinterpret_cast<const float4*>(
        up_decoder_w + (size_t)d0 * DICT + f0);
    const int RS4 = DICT / 4;
#pragma unroll
    for (int it = 0; it < (DH * FT / 4) / 256; it++) {
        int idx = t + 256 * it;
        int row = idx >> 4;                    // / (FT/4)
        int c4  = idx & 15;
        float4 v = src[(size_t)row * RS4 + c4];
        float* dst = &s[row * SROW + c4 * 4];
        dst[0] = v.x; dst[1] = v.y; dst[2] = v.z; dst[3] = v.w;
    }
    __syncthreads();

    const int warp = t >> 5;
    const int lane = t & 31;
    for (int p = warp; p < cnt; p += 8) {
        uint4 rec = g_bpairs[tile * CAP + p];
        const int fl = (int)rec.z - f0;
        const float* drow = down_encoder_w + (size_t)rec.y * DDIM + d0;
        float acc = 0.f;
#pragma unroll
        for (int m = 0; m < DH / 32; m++) {    // 2 iters, conflict-free smem
            int dd = lane + 32 * m;
            acc += s[dd * SROW + fl] * drow[dd];
        }
#pragma unroll
        for (int o = 16; o > 0; o >>= 1)
            acc += __shfl_xor_sync(0xffffffffu, acc, o);
        if (lane == 0)
            atomicAdd(&out[rec.x], acc * __uint_as_float(rec.w));
    }
}

// ---------------------------------------------------------------------------
extern "C" void kernel_launch(void* const* d_in, const int* in_sizes, int n_in,
                              void* d_out, int out_size)
{
    const float* up_vals        = (const float*)d_in[0];
    const float* up_decoder_w   = (const float*)d_in[1];
    const float* down_encoder_w = (const float*)d_in[2];
    const float* up_encoder_w   = (const float*)d_in[3];
    const float* b_dec          = (const float*)d_in[4];
    const int*   up_indices     = (const int*)d_in[5];
    const int*   down_indices   = (const int*)d_in[6];
    const int*   connections    = (const int*)d_in[7];
    float*       out            = (float*)d_out;

    k1_kernel<<<NK1, 256>>>(up_vals, up_indices, down_indices, connections,
                            up_encoder_w, b_dec, out);
    k2_kernel<<<NK2, 256>>>(up_decoder_w, down_encoder_w, up_indices, out);
}